// round 2
// baseline (speedup 1.0000x reference)
#include <cuda_runtime.h>

#define SGRID 1024
#define BSHIFT 12
#define NB (1 << 18)          // 2^30 keys >> 12 -> 2^18 buckets
#define MAXN 400000
#define MAXM (MAXN * 26)

static __device__ int d_keys[MAXN];
static __device__ int d_cnt[NB];
static __device__ int d_fill[NB];
static __device__ int d_offs[NB + 1];
static __device__ int d_partials[256];
static __device__ int d_bkey[MAXN];
static __device__ int d_bidx[MAXN];
static __device__ int d_outrow[MAXN];
static __device__ int d_gidx[MAXN];
static __device__ int d_mr[MAXM];
static __device__ int d_mj[MAXM];
static __device__ int d_mk[MAXM];
static __device__ int d_mcount;

// ---------------- bucket build ----------------

__global__ void k_zero() {
    int t = blockIdx.x * blockDim.x + threadIdx.x;
    int stride = gridDim.x * blockDim.x;
    for (int x = t; x < NB; x += stride) { d_cnt[x] = 0; d_fill[x] = 0; }
    if (t == 0) d_mcount = 0;
}

__global__ void k_keys_hist(const int* __restrict__ coords, int n) {
    int i = blockIdx.x * blockDim.x + threadIdx.x;
    if (i >= n) return;
    int key = (coords[3 * i] * SGRID + coords[3 * i + 1]) * SGRID + coords[3 * i + 2];
    d_keys[i] = key;
    atomicAdd(&d_cnt[key >> BSHIFT], 1);
}

__global__ void k_scan_block() {          // 256 blocks x 1024 threads over NB
    __shared__ int sh[1024];
    int b = blockIdx.x;
    int tid = threadIdx.x;
    int gid = b * 1024 + tid;
    int v = d_cnt[gid];
    sh[tid] = v;
#pragma unroll
    for (int off = 1; off < 1024; off <<= 1) {
        __syncthreads();
        int t = (tid >= off) ? sh[tid - off] : 0;
        __syncthreads();
        sh[tid] += t;
    }
    d_offs[gid] = sh[tid] - v;            // block-local exclusive
    if (tid == 1023) d_partials[b] = sh[tid];
}

__global__ void k_scan_partials() {       // 1 block x 256
    __shared__ int sh[256];
    int tid = threadIdx.x;
    int v = d_partials[tid];
    sh[tid] = v;
#pragma unroll
    for (int off = 1; off < 256; off <<= 1) {
        __syncthreads();
        int t = (tid >= off) ? sh[tid - off] : 0;
        __syncthreads();
        sh[tid] += t;
    }
    d_partials[tid] = sh[tid] - v;        // exclusive base per block
    if (tid == 255) d_offs[NB] = sh[255]; // total
}

__global__ void k_scan_add() {
    int gid = blockIdx.x * blockDim.x + threadIdx.x;
    if (gid < NB) d_offs[gid] += d_partials[gid >> 10];
}

__global__ void k_scatter(int n) {
    int i = blockIdx.x * blockDim.x + threadIdx.x;
    if (i >= n) return;
    int key = d_keys[i];
    int b = key >> BSHIFT;
    int p = d_offs[b] + atomicAdd(&d_fill[b], 1);
    d_bkey[p] = key;
    d_bidx[p] = i;
}

// rank within sorted order (keys unique): rank = bucket base + #smaller in bucket
__global__ void k_rank(int n) {
    int i = blockIdx.x * blockDim.x + threadIdx.x;
    if (i >= n) return;
    int key = d_keys[i];
    int b = key >> BSHIFT;
    int s = d_offs[b], e = d_offs[b + 1];
    int c = 0;
    for (int t = s; t < e; t++) c += (d_bkey[t] < key);
    int r = s + c;
    d_outrow[i] = r;
    d_gidx[r] = i;
}

// ---------------- main gathered GEMM: out[r] = F[gidx[r]] @ W[13] ----------------

#define FSP 68   // Fs row pitch (floats); 68 % 32 == 4 -> conflict-free transpose writes

__global__ void __launch_bounds__(128) k_gemm(const float* __restrict__ F,
                                              const float* __restrict__ W,
                                              float* __restrict__ out, int n) {
    __shared__ __align__(16) float Ws[64 * 64];   // W[13][ci][co]
    __shared__ __align__(16) float Fs[64 * FSP];  // transposed: Fs[ci][row]
    int tid = threadIdx.x;

    const float4* Wc = (const float4*)(W + 13 * 64 * 64);
    for (int x = tid; x < 1024; x += 128) ((float4*)Ws)[x] = Wc[x];

    int row0 = blockIdx.x * 64;
    int lrow = tid >> 1;          // 0..63
    int half = tid & 1;           // 2 threads per row -> full 32B sectors
    int gr = row0 + lrow;
    int gi = (gr < n) ? d_gidx[gr] : d_gidx[0];
    const float4* src = (const float4*)(F + (long long)gi * 64);
#pragma unroll
    for (int k = 0; k < 8; k++) {
        int chunk = k * 2 + half; // 0..15
        float4 v = src[chunk];
        int ci = chunk * 4;
        Fs[(ci + 0) * FSP + lrow] = v.x;
        Fs[(ci + 1) * FSP + lrow] = v.y;
        Fs[(ci + 2) * FSP + lrow] = v.z;
        Fs[(ci + 3) * FSP + lrow] = v.w;
    }
    __syncthreads();

    int cg = tid & 15, rg = tid >> 4;   // 16 col-groups x 8 row-groups
    int c0 = cg * 4, r0 = rg * 8;       // 8 rows x 4 cols per thread

    unsigned long long acc[8][2];
#pragma unroll
    for (int u = 0; u < 8; u++) { acc[u][0] = 0ull; acc[u][1] = 0ull; }

#pragma unroll 8
    for (int ci = 0; ci < 64; ci++) {
        float4 a0 = *(const float4*)&Fs[ci * FSP + r0];
        float4 a1 = *(const float4*)&Fs[ci * FSP + r0 + 4];
        unsigned long long b01 = *(const unsigned long long*)&Ws[ci * 64 + c0];
        unsigned long long b23 = *(const unsigned long long*)&Ws[ci * 64 + c0 + 2];
        float av[8] = {a0.x, a0.y, a0.z, a0.w, a1.x, a1.y, a1.z, a1.w};
#pragma unroll
        for (int u = 0; u < 8; u++) {
            unsigned long long aa;
            asm("mov.b64 %0, {%1, %2};" : "=l"(aa) : "f"(av[u]), "f"(av[u]));
            asm("fma.rn.f32x2 %0, %1, %2, %3;"
                : "=l"(acc[u][0]) : "l"(aa), "l"(b01), "l"(acc[u][0]));
            asm("fma.rn.f32x2 %0, %1, %2, %3;"
                : "=l"(acc[u][1]) : "l"(aa), "l"(b23), "l"(acc[u][1]));
        }
    }

#pragma unroll
    for (int u = 0; u < 8; u++) {
        int gr2 = row0 + r0 + u;
        if (gr2 < n) {
            float x0, x1, x2, x3;
            asm("mov.b64 {%0, %1}, %2;" : "=f"(x0), "=f"(x1) : "l"(acc[u][0]));
            asm("mov.b64 {%0, %1}, %2;" : "=f"(x2), "=f"(x3) : "l"(acc[u][1]));
            *(float4*)&out[(long long)gr2 * 64 + c0] = make_float4(x0, x1, x2, x3);
        }
    }
}

// ---------------- sparse corrections: 9 (dx,dy) probe groups, z in {-1,0,1} ----------------

__global__ void k_probe(int n) {
    int t = blockIdx.x * blockDim.x + threadIdx.x;
    if (t >= n * 9) return;
    int i = t / 9, g = t % 9;
    int key = d_keys[i];
    int q = key + (g / 3 - 1) * (SGRID * SGRID) + (g % 3 - 1) * SGRID;
    int lo = (q - 1) >> BSHIFT, hi = (q + 1) >> BSHIFT;
    int s = d_offs[lo], e = d_offs[hi + 1];   // contiguous across adjacent buckets
    for (int u = s; u < e; u++) {
        int d = d_bkey[u] - q;
        if (d < -1 || d > 1) continue;
        if (d == 0 && g == 4) continue;       // self (k=13) handled by dense GEMM
        int pos = atomicAdd(&d_mcount, 1);
        if (pos < MAXM) {
            d_mr[pos] = d_outrow[i];
            d_mj[pos] = d_bidx[u];
            d_mk[pos] = g * 3 + d + 1;        // row-major {-1,0,1}^3 kernel index
        }
    }
}

__global__ void k_apply(const float* __restrict__ F, const float* __restrict__ W,
                        float* __restrict__ out) {
    int warp = (blockIdx.x * blockDim.x + threadIdx.x) >> 5;
    int lane = threadIdx.x & 31;
    int nwarps = (gridDim.x * blockDim.x) >> 5;
    int total = d_mcount;
    if (total > MAXM) total = MAXM;
    for (int m = warp; m < total; m += nwarps) {
        int r = d_mr[m], j = d_mj[m], k = d_mk[m];
        float fv0 = F[j * 64 + lane];
        float fv1 = F[j * 64 + 32 + lane];
        const float* Wk = W + k * 64 * 64;
        float a0 = 0.f, a1 = 0.f;
#pragma unroll
        for (int ci = 0; ci < 32; ci++) {
            float f = __shfl_sync(0xffffffffu, fv0, ci);
            a0 += f * Wk[ci * 64 + lane];
            a1 += f * Wk[ci * 64 + 32 + lane];
        }
#pragma unroll
        for (int ci = 0; ci < 32; ci++) {
            float f = __shfl_sync(0xffffffffu, fv1, ci);
            a0 += f * Wk[(ci + 32) * 64 + lane];
            a1 += f * Wk[(ci + 32) * 64 + 32 + lane];
        }
        atomicAdd(&out[r * 64 + lane], a0);
        atomicAdd(&out[r * 64 + 32 + lane], a1);
    }
}

// ---------------- launch ----------------

extern "C" void kernel_launch(void* const* d_in, const int* in_sizes, int n_in,
                              void* d_out, int out_size) {
    const float* F = (const float*)d_in[0];       // [N,64] features
    const float* W = (const float*)d_in[1];       // [27,64,64] kernel
    const int* coords = (const int*)d_in[2];      // [N,3]
    int n = in_sizes[2] / 3;
    if (n > MAXN) n = MAXN;
    float* out = (float*)d_out;

    k_zero<<<256, 256>>>();
    k_keys_hist<<<(n + 255) / 256, 256>>>(coords, n);
    k_scan_block<<<NB / 1024, 1024>>>();
    k_scan_partials<<<1, 256>>>();
    k_scan_add<<<NB / 256, 256>>>();
    k_scatter<<<(n + 255) / 256, 256>>>(n);
    k_rank<<<(n + 255) / 256, 256>>>(n);
    k_gemm<<<(n + 63) / 64, 128>>>(F, W, out, n);
    k_probe<<<(n * 9 + 255) / 256, 256>>>(n);
    k_apply<<<256, 256>>>(F, W, out);
}

// round 4
// speedup vs baseline: 1.0827x; 1.0827x over previous
#include <cuda_runtime.h>
#include <cstdint>

#define SGRID 1024
#define BSHIFT 13
#define NB (1 << 17)
#define MAXN 400000
#define MAXM (1 << 20)

static __device__ int d_keys[MAXN];
static __device__ int d_cnt[NB];
static __device__ int d_fill[NB];
static __device__ int d_offs[NB + 1];
static __device__ int d_partials[128];
static __device__ int d_bkey[MAXN];
static __device__ int d_bidx[MAXN];
static __device__ int d_outrow[MAXN];
static __device__ int d_gidx[MAXN];
static __device__ int d_mi[MAXM];      // point index (rank resolved later)
static __device__ int d_mj[MAXM];
static __device__ int d_mk[MAXM];
static __device__ int d_mcount;
static __device__ __align__(16) unsigned d_Wt[4096];  // W[13] as tf32 bits, [ci][co]

__device__ __forceinline__ unsigned f2tf32(float x) {
    unsigned o;
    asm("cvt.rna.tf32.f32 %0, %1;" : "=r"(o) : "f"(x));
    return o;
}

// ---------------- bucket build ----------------

__global__ void k_zero(const float* __restrict__ W) {
    int t = blockIdx.x * blockDim.x + threadIdx.x;
    int stride = gridDim.x * blockDim.x;
    for (int x = t; x < NB; x += stride) { d_cnt[x] = 0; d_fill[x] = 0; }
    if (t == 0) d_mcount = 0;
    if (t < 4096) d_Wt[t] = f2tf32(W[13 * 4096 + t]);
}

__global__ void k_keys_hist(const int* __restrict__ coords, int n) {
    int i = blockIdx.x * blockDim.x + threadIdx.x;
    if (i >= n) return;
    int key = (coords[3 * i] * SGRID + coords[3 * i + 1]) * SGRID + coords[3 * i + 2];
    d_keys[i] = key;
    atomicAdd(&d_cnt[key >> BSHIFT], 1);
}

__global__ void k_scan_block() {           // 128 blocks x 1024 threads
    __shared__ int sh[1024];
    int b = blockIdx.x, tid = threadIdx.x;
    int gid = b * 1024 + tid;
    int v = d_cnt[gid];
    sh[tid] = v;
#pragma unroll
    for (int off = 1; off < 1024; off <<= 1) {
        __syncthreads();
        int t = (tid >= off) ? sh[tid - off] : 0;
        __syncthreads();
        sh[tid] += t;
    }
    d_offs[gid] = sh[tid] - v;
    if (tid == 1023) d_partials[b] = sh[tid];
}

__global__ void k_scan_partials() {        // 1 block x 128
    __shared__ int sh[128];
    int tid = threadIdx.x;
    int v = d_partials[tid];
    sh[tid] = v;
#pragma unroll
    for (int off = 1; off < 128; off <<= 1) {
        __syncthreads();
        int t = (tid >= off) ? sh[tid - off] : 0;
        __syncthreads();
        sh[tid] += t;
    }
    d_partials[tid] = sh[tid] - v;
    if (tid == 127) d_offs[NB] = sh[127];
}

__global__ void k_scan_add() {
    int gid = blockIdx.x * blockDim.x + threadIdx.x;
    if (gid < NB) d_offs[gid] += d_partials[gid >> 10];
}

__global__ void k_scatter(int n) {
    int i = blockIdx.x * blockDim.x + threadIdx.x;
    if (i >= n) return;
    int key = d_keys[i];
    int b = key >> BSHIFT;
    int p = d_offs[b] + atomicAdd(&d_fill[b], 1);
    d_bkey[p] = key;
    d_bidx[p] = i;
}

__global__ void k_rank(int n) {
    int i = blockIdx.x * blockDim.x + threadIdx.x;
    if (i >= n) return;
    int key = d_keys[i];
    int b = key >> BSHIFT;
    int s = d_offs[b], e = d_offs[b + 1];
    int c = 0;
    for (int t = s; t < e; t++) c += (d_bkey[t] < key);
    int r = s + c;
    d_outrow[i] = r;
    d_gidx[r] = i;
}

// ---------------- dense gathered GEMM via mma.sync tf32 ----------------
// CTA: 128 threads (4 warps), tile M=128 x N=64, K=64.
// Fs[128][68] (A, tf32 bits), Ws[64][72] (B = W13, tf32 bits).

#define FP 68
#define WP 72
#define SMEM_GEMM ((64 * WP + 128 * FP) * 4)

__global__ void __launch_bounds__(128) k_gemm_tc(const float* __restrict__ F,
                                                 float* __restrict__ out, int n) {
    extern __shared__ __align__(16) unsigned smem[];
    unsigned* Ws = smem;              // [64][WP]
    unsigned* Fs = smem + 64 * WP;    // [128][FP]
    int tid = threadIdx.x, lane = tid & 31, warp = tid >> 5;

    // B: copy pre-converted W13 (coalesced, pitched)
#pragma unroll
    for (int x = tid; x < 1024; x += 128) {
        int r = x >> 4, c4 = x & 15;
        uint4 v = ((const uint4*)d_Wt)[x];
        *(uint4*)&Ws[r * WP + c4 * 4] = v;
    }

    // A: gather one row per thread, convert to tf32, store pitched
    int row0 = blockIdx.x * 128;
    {
        int gr = row0 + tid;
        int gi = d_gidx[(gr < n) ? gr : 0];
        const float4* src = (const float4*)(F + (size_t)gi * 64);
#pragma unroll
        for (int c = 0; c < 16; c++) {
            float4 v = src[c];
            unsigned* dst = &Fs[tid * FP + c * 4];
            dst[0] = f2tf32(v.x); dst[1] = f2tf32(v.y);
            dst[2] = f2tf32(v.z); dst[3] = f2tf32(v.w);
        }
    }
    __syncthreads();

    int g = lane >> 2, t = lane & 3;
    int mBase = warp * 32;
    float acc[2][8][4];
#pragma unroll
    for (int mt = 0; mt < 2; mt++)
#pragma unroll
        for (int nt = 0; nt < 8; nt++)
#pragma unroll
            for (int u = 0; u < 4; u++) acc[mt][nt][u] = 0.f;

#pragma unroll
    for (int k0 = 0; k0 < 64; k0 += 8) {
        unsigned a[2][4];
#pragma unroll
        for (int mt = 0; mt < 2; mt++) {
            int r = mBase + mt * 16;
            a[mt][0] = Fs[(r + g) * FP + k0 + t];
            a[mt][1] = Fs[(r + g + 8) * FP + k0 + t];
            a[mt][2] = Fs[(r + g) * FP + k0 + t + 4];
            a[mt][3] = Fs[(r + g + 8) * FP + k0 + t + 4];
        }
#pragma unroll
        for (int nt = 0; nt < 8; nt++) {
            unsigned b0 = Ws[(k0 + t) * WP + nt * 8 + g];
            unsigned b1 = Ws[(k0 + t + 4) * WP + nt * 8 + g];
#pragma unroll
            for (int mt = 0; mt < 2; mt++) {
                asm volatile(
                    "mma.sync.aligned.m16n8k8.row.col.f32.tf32.tf32.f32 "
                    "{%0,%1,%2,%3},{%4,%5,%6,%7},{%8,%9},{%0,%1,%2,%3};"
                    : "+f"(acc[mt][nt][0]), "+f"(acc[mt][nt][1]),
                      "+f"(acc[mt][nt][2]), "+f"(acc[mt][nt][3])
                    : "r"(a[mt][0]), "r"(a[mt][1]), "r"(a[mt][2]), "r"(a[mt][3]),
                      "r"(b0), "r"(b1));
            }
        }
    }

    // epilogue: c0,c1 -> (row g, cols 2t,2t+1); c2,c3 -> row g+8
#pragma unroll
    for (int mt = 0; mt < 2; mt++) {
        int rA = row0 + mBase + mt * 16 + g;
        int rB = rA + 8;
#pragma unroll
        for (int nt = 0; nt < 8; nt++) {
            int c = nt * 8 + 2 * t;
            if (rA < n) *(float2*)&out[(size_t)rA * 64 + c] =
                make_float2(acc[mt][nt][0], acc[mt][nt][1]);
            if (rB < n) *(float2*)&out[(size_t)rB * 64 + c] =
                make_float2(acc[mt][nt][2], acc[mt][nt][3]);
        }
    }
}

// ---------------- sparse corrections ----------------

__global__ void k_probe(int n) {
    int tt = blockIdx.x * blockDim.x + threadIdx.x;
    if (tt >= n * 9) return;
    int i = tt / 9, gg = tt % 9;
    int key = d_keys[i];
    int q = key + (gg / 3 - 1) * (SGRID * SGRID) + (gg % 3 - 1) * SGRID;
    int lo = (q - 1) >> BSHIFT, hi = (q + 1) >> BSHIFT;
    int s = d_offs[lo], e = d_offs[hi + 1];
    for (int u = s; u < e; u++) {
        int d = d_bkey[u] - q;
        if (d < -1 || d > 1) continue;
        if (d == 0 && gg == 4) continue;
        int pos = atomicAdd(&d_mcount, 1);
        if (pos < MAXM) {
            d_mi[pos] = i;
            d_mj[pos] = d_bidx[u];
            d_mk[pos] = gg * 3 + d + 1;
        }
    }
}

__global__ void k_apply(const float* __restrict__ F, const float* __restrict__ W,
                        float* __restrict__ out) {
    int warp = (blockIdx.x * blockDim.x + threadIdx.x) >> 5;
    int lane = threadIdx.x & 31;
    int nwarps = (gridDim.x * blockDim.x) >> 5;
    int total = d_mcount;
    if (total > MAXM) total = MAXM;
    for (int m = warp; m < total; m += nwarps) {
        int r = d_outrow[d_mi[m]], j = d_mj[m], k = d_mk[m];
        float fv0 = F[j * 64 + lane];
        float fv1 = F[j * 64 + 32 + lane];
        const float* Wk = W + k * 64 * 64;
        float a0 = 0.f, a1 = 0.f;
#pragma unroll
        for (int ci = 0; ci < 32; ci++) {
            float f = __shfl_sync(0xffffffffu, fv0, ci);
            a0 += f * Wk[ci * 64 + lane];
            a1 += f * Wk[ci * 64 + 32 + lane];
        }
#pragma unroll
        for (int ci = 0; ci < 32; ci++) {
            float f = __shfl_sync(0xffffffffu, fv1, ci);
            a0 += f * Wk[(ci + 32) * 64 + lane];
            a1 += f * Wk[(ci + 32) * 64 + 32 + lane];
        }
        atomicAdd(&out[r * 64 + lane], a0);
        atomicAdd(&out[r * 64 + 32 + lane], a1);
    }
}

// ---------------- launch ----------------

extern "C" void kernel_launch(void* const* d_in, const int* in_sizes, int n_in,
                              void* d_out, int out_size) {
    const float* F = (const float*)d_in[0];
    const float* W = (const float*)d_in[1];
    const int* coords = (const int*)d_in[2];
    int n = in_sizes[2] / 3;
    if (n > MAXN) n = MAXN;
    float* out = (float*)d_out;

    static cudaStream_t s2 = nullptr;
    static cudaEvent_t e1 = nullptr, e2 = nullptr;
    if (!s2) {   // first (uncaptured correctness) call creates; capture call reuses
        cudaStreamCreateWithFlags(&s2, cudaStreamNonBlocking);
        cudaEventCreateWithFlags(&e1, cudaEventDisableTiming);
        cudaEventCreateWithFlags(&e2, cudaEventDisableTiming);
        cudaFuncSetAttribute(k_gemm_tc, cudaFuncAttributeMaxDynamicSharedMemorySize, SMEM_GEMM);
    }

    k_zero<<<256, 256>>>(W);
    k_keys_hist<<<(n + 255) / 256, 256>>>(coords, n);
    k_scan_block<<<NB / 1024, 1024>>>();
    k_scan_partials<<<1, 128>>>();
    k_scan_add<<<NB / 256, 256>>>();
    k_scatter<<<(n + 255) / 256, 256>>>(n);

    // fork: probe (independent of rank/gemm) runs concurrently on s2
    cudaEventRecord(e1, 0);
    cudaStreamWaitEvent(s2, e1, 0);
    k_probe<<<(n * 9 + 255) / 256, 256, 0, s2>>>(n);
    cudaEventRecord(e2, s2);

    k_rank<<<(n + 255) / 256, 256>>>(n);
    k_gemm_tc<<<(n + 127) / 128, 128, SMEM_GEMM>>>(F, out, n);

    // join, then apply corrections on top of GEMM output
    cudaStreamWaitEvent(0, e2, 0);
    k_apply<<<256, 256>>>(F, W, out);
}

// round 5
// speedup vs baseline: 1.2026x; 1.1107x over previous
#include <cuda_runtime.h>
#include <cuda_fp16.h>
#include <cstdint>

#define SGRID 1024
#define BSHIFT 13
#define NB (1 << 17)
#define NBLK 128            // scan blocks (NB / 1024)
#define MAXN 400000
#define MAXM (1 << 20)

static __device__ int d_keys[MAXN];
static __device__ int d_cnt[NB];
static __device__ int d_offs[NB + 1];
static __device__ unsigned long long d_look[NBLK];   // (flag<<62)|value
static __device__ int d_bkey[MAXN];
static __device__ int d_bidx[MAXN];
static __device__ int d_outrow[MAXN];
static __device__ int d_gidx[MAXN];
static __device__ int d_mi[MAXM];
static __device__ int d_mj[MAXM];
static __device__ int d_mk[MAXM];
static __device__ int d_mcount;
static __device__ __align__(16) __half d_Wh[4096];   // W[13]^T as half: [co][ci]

// ---------------- prep ----------------

__global__ void k_zero(const float* __restrict__ W) {
    int t = blockIdx.x * blockDim.x + threadIdx.x;
    int stride = gridDim.x * blockDim.x;
    for (int x = t; x < NB; x += stride) d_cnt[x] = 0;
    if (t < NBLK) d_look[t] = 0ull;
    if (t == 0) d_mcount = 0;
    if (t < 4096) {
        int co = t >> 6, ci = t & 63;
        d_Wh[t] = __float2half(W[13 * 4096 + ci * 64 + co]);
    }
}

__global__ void k_keys_hist(const int* __restrict__ coords, int n) {
    int i = blockIdx.x * blockDim.x + threadIdx.x;
    if (i >= n) return;
    int key = (coords[3 * i] * SGRID + coords[3 * i + 1]) * SGRID + coords[3 * i + 2];
    d_keys[i] = key;
    atomicAdd(&d_cnt[key >> BSHIFT], 1);
}

// single-pass scan with decoupled lookback: 128 blocks x 1024 threads, all co-resident
__global__ void __launch_bounds__(1024) k_scan() {
    __shared__ int sh[1024];
    __shared__ int sh_excl;
    int b = blockIdx.x, tid = threadIdx.x;
    int gid = b * 1024 + tid;
    int v = d_cnt[gid];
    sh[tid] = v;
#pragma unroll
    for (int off = 1; off < 1024; off <<= 1) {
        __syncthreads();
        int t = (tid >= off) ? sh[tid - off] : 0;
        __syncthreads();
        sh[tid] += t;
    }
    __syncthreads();
    if (tid == 0) {
        int agg = sh[1023];
        volatile unsigned long long* look = (volatile unsigned long long*)d_look;
        int excl = 0;
        if (b == 0) {
            look[0] = (2ull << 62) | (unsigned)agg;
        } else {
            look[b] = (1ull << 62) | (unsigned)agg;
            int j = b - 1;
            for (;;) {
                unsigned long long w = look[j];
                unsigned long long f = w >> 62;
                if (f == 0) continue;
                excl += (int)(w & 0x3FFFFFFFFFFFFFFFull);
                if (f == 2) break;
                j--;
            }
            look[b] = (2ull << 62) | (unsigned)(excl + agg);
        }
        sh_excl = excl;
    }
    __syncthreads();
    int base = sh_excl;
    d_offs[gid] = base + sh[tid] - v;
    if (gid == NB - 1) d_offs[NB] = base + sh[1023];
}

__global__ void k_scatter(int n) {
    int i = blockIdx.x * blockDim.x + threadIdx.x;
    if (i >= n) return;
    int key = d_keys[i];
    int b = key >> BSHIFT;
    int p = d_offs[b] + atomicSub(&d_cnt[b], 1) - 1;
    d_bkey[p] = key;
    d_bidx[p] = i;
}

__global__ void k_rank(int n) {
    int i = blockIdx.x * blockDim.x + threadIdx.x;
    if (i >= n) return;
    int key = d_keys[i];
    int b = key >> BSHIFT;
    int s = d_offs[b], e = d_offs[b + 1];
    int c = 0;
    for (int t = s; t < e; t++) c += (d_bkey[t] < key);
    int r = s + c;
    d_outrow[i] = r;
    d_gidx[r] = i;
}

// ---------------- dense gathered GEMM: fp16 mma.m16n8k16 ----------------
// CTA: 128 threads (4 warps), tile M=128 x N=64, K=64.

#define FHP 72   // Fs pitch in halves: (4g+t) mod 32 distinct -> conflict-free frag loads
#define WHP 72

__global__ void __launch_bounds__(128) k_gemm_tc(const float* __restrict__ F,
                                                 float* __restrict__ out, int n) {
    __shared__ __align__(16) __half Ws[64 * WHP];
    __shared__ __align__(16) __half Fs[128 * FHP];
    int tid = threadIdx.x, lane = tid & 31, warp = tid >> 5;

    // B: copy pre-converted W13^T ([co][ci] halves), repitch 64 -> 72
#pragma unroll
    for (int k = 0; k < 8; k++) {
        int x = tid + 128 * k;            // 0..1023
        int r = x >> 4, c = x & 15;       // row, 4-half chunk
        uint2 v = ((const uint2*)d_Wh)[x];
        *(uint2*)&Ws[r * WHP + c * 4] = v;
    }

    // A: gather one row per thread, convert fp32 -> fp16
    int row0 = blockIdx.x * 128;
    {
        int gr = row0 + tid;
        int gi = d_gidx[(gr < n) ? gr : 0];
        const float4* src = (const float4*)(F + (size_t)gi * 64);
#pragma unroll
        for (int c = 0; c < 16; c++) {
            float4 v = src[c];
            __half2 h0 = __floats2half2_rn(v.x, v.y);
            __half2 h1 = __floats2half2_rn(v.z, v.w);
            *(__half2*)&Fs[tid * FHP + c * 4] = h0;
            *(__half2*)&Fs[tid * FHP + c * 4 + 2] = h1;
        }
    }
    __syncthreads();

    int g = lane >> 2, t = lane & 3;
    int mBase = warp * 32;
    float acc[2][8][4];
#pragma unroll
    for (int mt = 0; mt < 2; mt++)
#pragma unroll
        for (int nt = 0; nt < 8; nt++)
#pragma unroll
            for (int u = 0; u < 4; u++) acc[mt][nt][u] = 0.f;

#pragma unroll
    for (int k0 = 0; k0 < 64; k0 += 16) {
        unsigned a[2][4];
#pragma unroll
        for (int mt = 0; mt < 2; mt++) {
            int r = mBase + mt * 16;
            a[mt][0] = *(const unsigned*)&Fs[(r + g) * FHP + k0 + 2 * t];
            a[mt][1] = *(const unsigned*)&Fs[(r + g + 8) * FHP + k0 + 2 * t];
            a[mt][2] = *(const unsigned*)&Fs[(r + g) * FHP + k0 + 2 * t + 8];
            a[mt][3] = *(const unsigned*)&Fs[(r + g + 8) * FHP + k0 + 2 * t + 8];
        }
#pragma unroll
        for (int nt = 0; nt < 8; nt++) {
            unsigned b0 = *(const unsigned*)&Ws[(nt * 8 + g) * WHP + k0 + 2 * t];
            unsigned b1 = *(const unsigned*)&Ws[(nt * 8 + g) * WHP + k0 + 2 * t + 8];
#pragma unroll
            for (int mt = 0; mt < 2; mt++) {
                asm volatile(
                    "mma.sync.aligned.m16n8k16.row.col.f32.f16.f16.f32 "
                    "{%0,%1,%2,%3},{%4,%5,%6,%7},{%8,%9},{%0,%1,%2,%3};"
                    : "+f"(acc[mt][nt][0]), "+f"(acc[mt][nt][1]),
                      "+f"(acc[mt][nt][2]), "+f"(acc[mt][nt][3])
                    : "r"(a[mt][0]), "r"(a[mt][1]), "r"(a[mt][2]), "r"(a[mt][3]),
                      "r"(b0), "r"(b1));
            }
        }
    }

    // epilogue: c0,c1 -> (row g, cols 2t,2t+1); c2,c3 -> row g+8
#pragma unroll
    for (int mt = 0; mt < 2; mt++) {
        int rA = row0 + mBase + mt * 16 + g;
        int rB = rA + 8;
#pragma unroll
        for (int nt = 0; nt < 8; nt++) {
            int c = nt * 8 + 2 * t;
            if (rA < n) *(float2*)&out[(size_t)rA * 64 + c] =
                make_float2(acc[mt][nt][0], acc[mt][nt][1]);
            if (rB < n) *(float2*)&out[(size_t)rB * 64 + c] =
                make_float2(acc[mt][nt][2], acc[mt][nt][3]);
        }
    }
}

// ---------------- sparse corrections ----------------

__global__ void k_probe(int n) {
    int tt = blockIdx.x * blockDim.x + threadIdx.x;
    if (tt >= n * 9) return;
    int i = tt / 9, gg = tt % 9;
    int key = d_keys[i];
    int q = key + (gg / 3 - 1) * (SGRID * SGRID) + (gg % 3 - 1) * SGRID;
    int lo = (q - 1) >> BSHIFT, hi = (q + 1) >> BSHIFT;
    int s = d_offs[lo], e = d_offs[hi + 1];
    for (int u = s; u < e; u++) {
        int d = d_bkey[u] - q;
        if (d < -1 || d > 1) continue;
        if (d == 0 && gg == 4) continue;
        int pos = atomicAdd(&d_mcount, 1);
        if (pos < MAXM) {
            d_mi[pos] = i;
            d_mj[pos] = d_bidx[u];
            d_mk[pos] = gg * 3 + d + 1;
        }
    }
}

__global__ void k_apply(const float* __restrict__ F, const float* __restrict__ W,
                        float* __restrict__ out) {
    int warp = (blockIdx.x * blockDim.x + threadIdx.x) >> 5;
    int lane = threadIdx.x & 31;
    int nwarps = (gridDim.x * blockDim.x) >> 5;
    int total = d_mcount;
    if (total > MAXM) total = MAXM;
    for (int m = warp; m < total; m += nwarps) {
        int r = d_outrow[d_mi[m]], j = d_mj[m], k = d_mk[m];
        float fv0 = F[j * 64 + lane];
        float fv1 = F[j * 64 + 32 + lane];
        const float* Wk = W + k * 64 * 64;
        float a0 = 0.f, a1 = 0.f;
#pragma unroll
        for (int ci = 0; ci < 32; ci++) {
            float f = __shfl_sync(0xffffffffu, fv0, ci);
            a0 += f * Wk[ci * 64 + lane];
            a1 += f * Wk[ci * 64 + 32 + lane];
        }
#pragma unroll
        for (int ci = 0; ci < 32; ci++) {
            float f = __shfl_sync(0xffffffffu, fv1, ci);
            a0 += f * Wk[(ci + 32) * 64 + lane];
            a1 += f * Wk[(ci + 32) * 64 + 32 + lane];
        }
        atomicAdd(&out[r * 64 + lane], a0);
        atomicAdd(&out[r * 64 + 32 + lane], a1);
    }
}

// ---------------- launch ----------------

extern "C" void kernel_launch(void* const* d_in, const int* in_sizes, int n_in,
                              void* d_out, int out_size) {
    const float* F = (const float*)d_in[0];
    const float* W = (const float*)d_in[1];
    const int* coords = (const int*)d_in[2];
    int n = in_sizes[2] / 3;
    if (n > MAXN) n = MAXN;
    float* out = (float*)d_out;

    static cudaStream_t s2 = nullptr;
    static cudaEvent_t e1 = nullptr, e2 = nullptr;
    if (!s2) {
        cudaStreamCreateWithFlags(&s2, cudaStreamNonBlocking);
        cudaEventCreateWithFlags(&e1, cudaEventDisableTiming);
        cudaEventCreateWithFlags(&e2, cudaEventDisableTiming);
    }

    k_zero<<<256, 256>>>(W);
    k_keys_hist<<<(n + 255) / 256, 256>>>(coords, n);
    k_scan<<<NBLK, 1024>>>();
    k_scatter<<<(n + 255) / 256, 256>>>(n);

    // fork: probe runs concurrently with rank + gemm
    cudaEventRecord(e1, 0);
    cudaStreamWaitEvent(s2, e1, 0);
    k_probe<<<(n * 9 + 255) / 256, 256, 0, s2>>>(n);
    cudaEventRecord(e2, s2);

    k_rank<<<(n + 255) / 256, 256>>>(n);
    k_gemm_tc<<<(n + 127) / 128, 128>>>(F, out, n);

    cudaStreamWaitEvent(0, e2, 0);
    k_apply<<<256, 256>>>(F, W, out);
}

// round 6
// speedup vs baseline: 1.2140x; 1.0095x over previous
#include <cuda_runtime.h>
#include <cuda_fp16.h>
#include <cstdint>

#define SGRID 1024
#define BSHIFT 12
#define NB (1 << 18)
#define NBLK 256            // scan blocks (NB / 1024)
#define MAXN 400000
#define MAXM (1 << 20)

static __device__ int d_keys[MAXN];
static __device__ int d_cnt[NB];                     // self-restoring: scatter returns it to 0
static __device__ int d_offs[NB + 1];
static __device__ unsigned long long d_look[NBLK];
static __device__ int2 d_bpair[MAXN];                // (key, idx)
static __device__ int d_outrow[MAXN];
static __device__ int d_gidx[MAXN];
static __device__ int d_mi[MAXM];
static __device__ int d_mj[MAXM];
static __device__ int d_mk[MAXM];
static __device__ int d_mcount;
static __device__ __align__(16) __half d_Wh[4096];   // W[13]^T as half: [co][ci]

// ---------------- fused init + keys + histogram ----------------

__global__ void k_keys_hist(const int* __restrict__ coords, const float* __restrict__ W, int n) {
    __shared__ int sc[768];
    int tid = threadIdx.x;
    int t = blockIdx.x * 256 + tid;

    // per-call init folded in (runs before scan/probe in stream order)
    if (t < NBLK) d_look[t] = 0ull;
    if (t == 0) d_mcount = 0;
    if (t < 4096) {
        int co = t >> 6, ci = t & 63;
        d_Wh[t] = __float2half(W[13 * 4096 + ci * 64 + co]);
    }

    // coalesced coord staging
    int base = blockIdx.x * 768;
#pragma unroll
    for (int x = tid; x < 768; x += 256) {
        int g = base + x;
        if (g < n * 3) sc[x] = coords[g];
    }
    __syncthreads();
    if (t >= n) return;
    int key = (sc[tid * 3] * SGRID + sc[tid * 3 + 1]) * SGRID + sc[tid * 3 + 2];
    d_keys[t] = key;
    atomicAdd(&d_cnt[key >> BSHIFT], 1);
}

// single-pass decoupled-lookback scan: 256 blocks x 1024 threads, co-resident
__global__ void __launch_bounds__(1024) k_scan() {
    __shared__ int sh[1024];
    __shared__ int sh_excl;
    int b = blockIdx.x, tid = threadIdx.x;
    int gid = b * 1024 + tid;
    int v = d_cnt[gid];
    sh[tid] = v;
#pragma unroll
    for (int off = 1; off < 1024; off <<= 1) {
        __syncthreads();
        int t = (tid >= off) ? sh[tid - off] : 0;
        __syncthreads();
        sh[tid] += t;
    }
    __syncthreads();
    if (tid == 0) {
        int agg = sh[1023];
        volatile unsigned long long* look = (volatile unsigned long long*)d_look;
        int excl = 0;
        if (b == 0) {
            look[0] = (2ull << 62) | (unsigned)agg;
        } else {
            look[b] = (1ull << 62) | (unsigned)agg;
            int j = b - 1;
            for (;;) {
                unsigned long long w = look[j];
                unsigned long long f = w >> 62;
                if (f == 0) continue;
                excl += (int)(w & 0x3FFFFFFFFFFFFFFFull);
                if (f == 2) break;
                j--;
            }
            look[b] = (2ull << 62) | (unsigned)(excl + agg);
        }
        sh_excl = excl;
    }
    __syncthreads();
    int base = sh_excl;
    d_offs[gid] = base + sh[tid] - v;
    if (gid == NB - 1) d_offs[NB] = base + sh[1023];
}

__global__ void k_scatter(int n) {
    int i = blockIdx.x * blockDim.x + threadIdx.x;
    if (i >= n) return;
    int key = d_keys[i];
    int b = key >> BSHIFT;
    int p = d_offs[b] + atomicSub(&d_cnt[b], 1) - 1;   // also restores d_cnt[b] -> 0
    d_bpair[p] = make_int2(key, i);
}

__global__ void k_rank(int n) {
    int i = blockIdx.x * blockDim.x + threadIdx.x;
    if (i >= n) return;
    int key = d_keys[i];
    int b = key >> BSHIFT;
    int s = d_offs[b], e = d_offs[b + 1];
    int c = 0;
    for (int t = s; t < e; t++) c += (d_bpair[t].x < key);
    int r = s + c;
    d_outrow[i] = r;
    d_gidx[r] = i;
}

// ---------------- dense gathered GEMM: fp16 mma.m16n8k16, M=128 x N=64, K=64 ----------------

#define FHP 72
#define WHP 72

__global__ void __launch_bounds__(128, 5) k_gemm_tc(const float* __restrict__ F,
                                                    float* __restrict__ out, int n) {
    __shared__ __align__(16) __half Ws[64 * WHP];
    __shared__ __align__(16) __half Fs[128 * FHP];
    int tid = threadIdx.x, lane = tid & 31, warp = tid >> 5;

#pragma unroll
    for (int k = 0; k < 8; k++) {
        int x = tid + 128 * k;
        int r = x >> 4, c = x & 15;
        uint2 v = ((const uint2*)d_Wh)[x];
        *(uint2*)&Ws[r * WHP + c * 4] = v;
    }

    int row0 = blockIdx.x * 128;
    {
        int gr = row0 + tid;
        int gi = d_gidx[(gr < n) ? gr : 0];
        const float4* src = (const float4*)(F + (size_t)gi * 64);
#pragma unroll
        for (int c = 0; c < 16; c++) {
            float4 v = src[c];
            *(__half2*)&Fs[tid * FHP + c * 4] = __floats2half2_rn(v.x, v.y);
            *(__half2*)&Fs[tid * FHP + c * 4 + 2] = __floats2half2_rn(v.z, v.w);
        }
    }
    __syncthreads();

    int g = lane >> 2, t = lane & 3;
    int mBase = warp * 32;
    float acc[2][8][4];
#pragma unroll
    for (int mt = 0; mt < 2; mt++)
#pragma unroll
        for (int nt = 0; nt < 8; nt++)
#pragma unroll
            for (int u = 0; u < 4; u++) acc[mt][nt][u] = 0.f;

#pragma unroll
    for (int k0 = 0; k0 < 64; k0 += 16) {
        unsigned a[2][4];
#pragma unroll
        for (int mt = 0; mt < 2; mt++) {
            int r = mBase + mt * 16;
            a[mt][0] = *(const unsigned*)&Fs[(r + g) * FHP + k0 + 2 * t];
            a[mt][1] = *(const unsigned*)&Fs[(r + g + 8) * FHP + k0 + 2 * t];
            a[mt][2] = *(const unsigned*)&Fs[(r + g) * FHP + k0 + 2 * t + 8];
            a[mt][3] = *(const unsigned*)&Fs[(r + g + 8) * FHP + k0 + 2 * t + 8];
        }
#pragma unroll
        for (int nt = 0; nt < 8; nt++) {
            unsigned b0 = *(const unsigned*)&Ws[(nt * 8 + g) * WHP + k0 + 2 * t];
            unsigned b1 = *(const unsigned*)&Ws[(nt * 8 + g) * WHP + k0 + 2 * t + 8];
#pragma unroll
            for (int mt = 0; mt < 2; mt++) {
                asm volatile(
                    "mma.sync.aligned.m16n8k16.row.col.f32.f16.f16.f32 "
                    "{%0,%1,%2,%3},{%4,%5,%6,%7},{%8,%9},{%0,%1,%2,%3};"
                    : "+f"(acc[mt][nt][0]), "+f"(acc[mt][nt][1]),
                      "+f"(acc[mt][nt][2]), "+f"(acc[mt][nt][3])
                    : "r"(a[mt][0]), "r"(a[mt][1]), "r"(a[mt][2]), "r"(a[mt][3]),
                      "r"(b0), "r"(b1));
            }
        }
    }

#pragma unroll
    for (int mt = 0; mt < 2; mt++) {
        int rA = row0 + mBase + mt * 16 + g;
        int rB = rA + 8;
#pragma unroll
        for (int nt = 0; nt < 8; nt++) {
            int c = nt * 8 + 2 * t;
            if (rA < n) *(float2*)&out[(size_t)rA * 64 + c] =
                make_float2(acc[mt][nt][0], acc[mt][nt][1]);
            if (rB < n) *(float2*)&out[(size_t)rB * 64 + c] =
                make_float2(acc[mt][nt][2], acc[mt][nt][3]);
        }
    }
}

// ---------------- sparse corrections ----------------

__global__ void k_probe(int n) {
    int tt = blockIdx.x * blockDim.x + threadIdx.x;
    if (tt >= n * 9) return;
    int i = tt / 9, gg = tt % 9;
    int key = d_keys[i];
    int q = key + (gg / 3 - 1) * (SGRID * SGRID) + (gg % 3 - 1) * SGRID;
    int lo = (q - 1) >> BSHIFT, hi = (q + 1) >> BSHIFT;
    int s = d_offs[lo], e = d_offs[hi + 1];
    for (int u = s; u < e; u++) {
        int2 kv = d_bpair[u];
        int d = kv.x - q;
        if (d < -1 || d > 1) continue;
        if (d == 0 && gg == 4) continue;
        int pos = atomicAdd(&d_mcount, 1);
        if (pos < MAXM) {
            d_mi[pos] = i;
            d_mj[pos] = kv.y;
            d_mk[pos] = gg * 3 + d + 1;
        }
    }
}

__global__ void k_apply(const float* __restrict__ F, const float* __restrict__ W,
                        float* __restrict__ out) {
    int warp = (blockIdx.x * blockDim.x + threadIdx.x) >> 5;
    int lane = threadIdx.x & 31;
    int nwarps = (gridDim.x * blockDim.x) >> 5;
    int total = d_mcount;
    if (total > MAXM) total = MAXM;
    for (int m = warp; m < total; m += nwarps) {
        int r = d_outrow[d_mi[m]], j = d_mj[m], k = d_mk[m];
        float fv0 = F[j * 64 + lane];
        float fv1 = F[j * 64 + 32 + lane];
        const float* Wk = W + k * 64 * 64;
        float a0 = 0.f, a1 = 0.f;
#pragma unroll
        for (int ci = 0; ci < 32; ci++) {
            float f = __shfl_sync(0xffffffffu, fv0, ci);
            a0 += f * Wk[ci * 64 + lane];
            a1 += f * Wk[ci * 64 + 32 + lane];
        }
#pragma unroll
        for (int ci = 0; ci < 32; ci++) {
            float f = __shfl_sync(0xffffffffu, fv1, ci);
            a0 += f * Wk[(ci + 32) * 64 + lane];
            a1 += f * Wk[(ci + 32) * 64 + 32 + lane];
        }
        atomicAdd(&out[r * 64 + lane], a0);
        atomicAdd(&out[r * 64 + 32 + lane], a1);
    }
}

// ---------------- launch ----------------

extern "C" void kernel_launch(void* const* d_in, const int* in_sizes, int n_in,
                              void* d_out, int out_size) {
    const float* F = (const float*)d_in[0];
    const float* W = (const float*)d_in[1];
    const int* coords = (const int*)d_in[2];
    int n = in_sizes[2] / 3;
    if (n > MAXN) n = MAXN;
    float* out = (float*)d_out;

    static cudaStream_t s2 = nullptr;
    static cudaEvent_t e1 = nullptr, e2 = nullptr;
    if (!s2) {
        cudaStreamCreateWithFlags(&s2, cudaStreamNonBlocking);
        cudaEventCreateWithFlags(&e1, cudaEventDisableTiming);
        cudaEventCreateWithFlags(&e2, cudaEventDisableTiming);
    }

    k_keys_hist<<<(n + 255) / 256, 256>>>(coords, W, n);
    k_scan<<<NBLK, 1024>>>();
    k_scatter<<<(n + 255) / 256, 256>>>(n);

    // fork: probe runs concurrently with rank + gemm
    cudaEventRecord(e1, 0);
    cudaStreamWaitEvent(s2, e1, 0);
    k_probe<<<(n * 9 + 255) / 256, 256, 0, s2>>>(n);
    cudaEventRecord(e2, s2);

    k_rank<<<(n + 255) / 256, 256>>>(n);
    k_gemm_tc<<<(n + 127) / 128, 128>>>(F, out, n);

    cudaStreamWaitEvent(0, e2, 0);
    k_apply<<<256, 256>>>(F, W, out);
}

// round 7
// speedup vs baseline: 1.2176x; 1.0030x over previous
#include <cuda_runtime.h>
#include <cuda_fp16.h>
#include <cstdint>

#define SGRID 1024
#define BSHIFT 12
#define NB (1 << 18)
#define NBLK 256            // scan blocks (NB / 1024)
#define MAXN 400000
#define MAXM (1 << 20)

static __device__ int d_keys[MAXN];
static __device__ int d_cnt[NB];                     // self-restoring: scatter returns it to 0
static __device__ int d_offs[NB + 1];
static __device__ unsigned long long d_look[NBLK];
static __device__ int2 d_bpair[MAXN];                // (key, idx)
static __device__ int d_gidx[MAXN];
static __device__ int d_mi[MAXM];                    // output row r
static __device__ int d_mj[MAXM];
static __device__ int d_mk[MAXM];
static __device__ int d_mcount;
static __device__ __align__(16) __half d_Wh[4096];   // W[13]^T as half: [co][ci]

// ---------------- fused init + keys + histogram ----------------

__global__ void k_keys_hist(const int* __restrict__ coords, const float* __restrict__ W, int n) {
    __shared__ int sc[768];
    int tid = threadIdx.x;
    int t = blockIdx.x * 256 + tid;

    if (t < NBLK) d_look[t] = 0ull;
    if (t == 0) d_mcount = 0;
    if (t < 4096) {
        int co = t >> 6, ci = t & 63;
        d_Wh[t] = __float2half(W[13 * 4096 + ci * 64 + co]);
    }

    int base = blockIdx.x * 768;
#pragma unroll
    for (int x = tid; x < 768; x += 256) {
        int g = base + x;
        if (g < n * 3) sc[x] = coords[g];
    }
    __syncthreads();
    if (t >= n) return;
    int key = (sc[tid * 3] * SGRID + sc[tid * 3 + 1]) * SGRID + sc[tid * 3 + 2];
    d_keys[t] = key;
    atomicAdd(&d_cnt[key >> BSHIFT], 1);
}

// single-pass decoupled-lookback scan: 256 blocks x 1024 threads, co-resident
__global__ void __launch_bounds__(1024) k_scan() {
    __shared__ int sh[1024];
    __shared__ int sh_excl;
    int b = blockIdx.x, tid = threadIdx.x;
    int gid = b * 1024 + tid;
    int v = d_cnt[gid];
    sh[tid] = v;
#pragma unroll
    for (int off = 1; off < 1024; off <<= 1) {
        __syncthreads();
        int t = (tid >= off) ? sh[tid - off] : 0;
        __syncthreads();
        sh[tid] += t;
    }
    __syncthreads();
    if (tid == 0) {
        int agg = sh[1023];
        volatile unsigned long long* look = (volatile unsigned long long*)d_look;
        int excl = 0;
        if (b == 0) {
            look[0] = (2ull << 62) | (unsigned)agg;
        } else {
            look[b] = (1ull << 62) | (unsigned)agg;
            int j = b - 1;
            for (;;) {
                unsigned long long w = look[j];
                unsigned long long f = w >> 62;
                if (f == 0) continue;
                excl += (int)(w & 0x3FFFFFFFFFFFFFFFull);
                if (f == 2) break;
                j--;
            }
            look[b] = (2ull << 62) | (unsigned)(excl + agg);
        }
        sh_excl = excl;
    }
    __syncthreads();
    int base = sh_excl;
    d_offs[gid] = base + sh[tid] - v;
    if (gid == NB - 1) d_offs[NB] = base + sh[1023];
}

__global__ void k_scatter(int n) {
    int i = blockIdx.x * blockDim.x + threadIdx.x;
    if (i >= n) return;
    int key = d_keys[i];
    int b = key >> BSHIFT;
    int p = d_offs[b] + atomicSub(&d_cnt[b], 1) - 1;   // restores d_cnt[b] -> 0
    d_bpair[p] = make_int2(key, i);
}

// ---------------- fused rank + neighbor probe: one thread per point ----------------

__global__ void __launch_bounds__(256) k_proberank(int n) {
    int i = blockIdx.x * blockDim.x + threadIdx.x;
    if (i >= n) return;
    int key = d_keys[i];

    // batch all segment bounds first: high MLP over L2-resident d_offs
    int q[9], s[9], e[9];
#pragma unroll
    for (int g = 0; g < 9; g++) {
        int dq = (g / 3 - 1) * (SGRID * SGRID) + (g % 3 - 1) * SGRID;
        q[g] = key + dq;
        int lo = (q[g] - 1) >> BSHIFT;
        int hi = (q[g] + 1) >> BSHIFT;
        s[g] = d_offs[lo];
        e[g] = d_offs[hi + 1];
    }

    // rank from center-group segment (superset of own bucket)
    int b = key >> BSHIFT;
    int rbase = d_offs[b];
    int cnt = 0;
    for (int u = s[4]; u < e[4]; u++) {
        int k2 = d_bpair[u].x;
        cnt += ((k2 >> BSHIFT) == b) & (k2 < key);
    }
    int r = rbase + cnt;
    d_gidx[r] = i;

    // neighbor matches -> correction list (r stored directly)
#pragma unroll
    for (int g = 0; g < 9; g++) {
        for (int u = s[g]; u < e[g]; u++) {
            int2 kv = d_bpair[u];
            int d = kv.x - q[g];
            if (d < -1 || d > 1) continue;
            if (d == 0 && g == 4) continue;
            int pos = atomicAdd(&d_mcount, 1);
            if (pos < MAXM) {
                d_mi[pos] = r;
                d_mj[pos] = kv.y;
                d_mk[pos] = g * 3 + d + 1;
            }
        }
    }
}

// ---------------- dense gathered GEMM: fp16 mma.m16n8k16, M=128 x N=64, K=64 ----------------

#define FHP 72
#define WHP 72

__global__ void __launch_bounds__(128, 5) k_gemm_tc(const float* __restrict__ F,
                                                    float* __restrict__ out, int n) {
    __shared__ __align__(16) __half Ws[64 * WHP];
    __shared__ __align__(16) __half Fs[128 * FHP];
    int tid = threadIdx.x, lane = tid & 31, warp = tid >> 5;

#pragma unroll
    for (int k = 0; k < 8; k++) {
        int x = tid + 128 * k;
        int r = x >> 4, c = x & 15;
        uint2 v = ((const uint2*)d_Wh)[x];
        *(uint2*)&Ws[r * WHP + c * 4] = v;
    }

    int row0 = blockIdx.x * 128;
    {
        int gr = row0 + tid;
        int gi = d_gidx[(gr < n) ? gr : 0];
        const float4* src = (const float4*)(F + (size_t)gi * 64);
#pragma unroll
        for (int c = 0; c < 16; c++) {
            float4 v = src[c];
            *(__half2*)&Fs[tid * FHP + c * 4] = __floats2half2_rn(v.x, v.y);
            *(__half2*)&Fs[tid * FHP + c * 4 + 2] = __floats2half2_rn(v.z, v.w);
        }
    }
    __syncthreads();

    int g = lane >> 2, t = lane & 3;
    int mBase = warp * 32;
    float acc[2][8][4];
#pragma unroll
    for (int mt = 0; mt < 2; mt++)
#pragma unroll
        for (int nt = 0; nt < 8; nt++)
#pragma unroll
            for (int u = 0; u < 4; u++) acc[mt][nt][u] = 0.f;

#pragma unroll
    for (int k0 = 0; k0 < 64; k0 += 16) {
        unsigned a[2][4];
#pragma unroll
        for (int mt = 0; mt < 2; mt++) {
            int r = mBase + mt * 16;
            a[mt][0] = *(const unsigned*)&Fs[(r + g) * FHP + k0 + 2 * t];
            a[mt][1] = *(const unsigned*)&Fs[(r + g + 8) * FHP + k0 + 2 * t];
            a[mt][2] = *(const unsigned*)&Fs[(r + g) * FHP + k0 + 2 * t + 8];
            a[mt][3] = *(const unsigned*)&Fs[(r + g + 8) * FHP + k0 + 2 * t + 8];
        }
#pragma unroll
        for (int nt = 0; nt < 8; nt++) {
            unsigned b0 = *(const unsigned*)&Ws[(nt * 8 + g) * WHP + k0 + 2 * t];
            unsigned b1 = *(const unsigned*)&Ws[(nt * 8 + g) * WHP + k0 + 2 * t + 8];
#pragma unroll
            for (int mt = 0; mt < 2; mt++) {
                asm volatile(
                    "mma.sync.aligned.m16n8k16.row.col.f32.f16.f16.f32 "
                    "{%0,%1,%2,%3},{%4,%5,%6,%7},{%8,%9},{%0,%1,%2,%3};"
                    : "+f"(acc[mt][nt][0]), "+f"(acc[mt][nt][1]),
                      "+f"(acc[mt][nt][2]), "+f"(acc[mt][nt][3])
                    : "r"(a[mt][0]), "r"(a[mt][1]), "r"(a[mt][2]), "r"(a[mt][3]),
                      "r"(b0), "r"(b1));
            }
        }
    }

#pragma unroll
    for (int mt = 0; mt < 2; mt++) {
        int rA = row0 + mBase + mt * 16 + g;
        int rB = rA + 8;
#pragma unroll
        for (int nt = 0; nt < 8; nt++) {
            int c = nt * 8 + 2 * t;
            if (rA < n) *(float2*)&out[(size_t)rA * 64 + c] =
                make_float2(acc[mt][nt][0], acc[mt][nt][1]);
            if (rB < n) *(float2*)&out[(size_t)rB * 64 + c] =
                make_float2(acc[mt][nt][2], acc[mt][nt][3]);
        }
    }
}

// ---------------- apply corrections ----------------

__global__ void k_apply(const float* __restrict__ F, const float* __restrict__ W,
                        float* __restrict__ out) {
    int warp = (blockIdx.x * blockDim.x + threadIdx.x) >> 5;
    int lane = threadIdx.x & 31;
    int nwarps = (gridDim.x * blockDim.x) >> 5;
    int total = d_mcount;
    if (total > MAXM) total = MAXM;
    for (int m = warp; m < total; m += nwarps) {
        int r = d_mi[m], j = d_mj[m], k = d_mk[m];
        float fv0 = F[j * 64 + lane];
        float fv1 = F[j * 64 + 32 + lane];
        const float* Wk = W + k * 64 * 64;
        float a0 = 0.f, a1 = 0.f;
#pragma unroll
        for (int ci = 0; ci < 32; ci++) {
            float f = __shfl_sync(0xffffffffu, fv0, ci);
            a0 += f * Wk[ci * 64 + lane];
            a1 += f * Wk[ci * 64 + 32 + lane];
        }
#pragma unroll
        for (int ci = 0; ci < 32; ci++) {
            float f = __shfl_sync(0xffffffffu, fv1, ci);
            a0 += f * Wk[(ci + 32) * 64 + lane];
            a1 += f * Wk[(ci + 32) * 64 + 32 + lane];
        }
        atomicAdd(&out[r * 64 + lane], a0);
        atomicAdd(&out[r * 64 + 32 + lane], a1);
    }
}

// ---------------- launch ----------------

extern "C" void kernel_launch(void* const* d_in, const int* in_sizes, int n_in,
                              void* d_out, int out_size) {
    const float* F = (const float*)d_in[0];
    const float* W = (const float*)d_in[1];
    const int* coords = (const int*)d_in[2];
    int n = in_sizes[2] / 3;
    if (n > MAXN) n = MAXN;
    float* out = (float*)d_out;

    k_keys_hist<<<(n + 255) / 256, 256>>>(coords, W, n);
    k_scan<<<NBLK, 1024>>>();
    k_scatter<<<(n + 255) / 256, 256>>>(n);
    k_proberank<<<(n + 255) / 256, 256>>>(n);
    k_gemm_tc<<<(n + 127) / 128, 128>>>(F, out, n);
    k_apply<<<256, 256>>>(F, W, out);
}

// round 8
// speedup vs baseline: 1.4588x; 1.1981x over previous
#include <cuda_runtime.h>
#include <cuda_fp16.h>
#include <cstdint>

#define SGRID 1024
#define BSHIFT 12
#define NB (1 << 18)
#define NBLK 256            // scan blocks (NB / 1024)
#define MAXN 400000
#define MAXM (1 << 20)

static __device__ int d_keys[MAXN];
static __device__ int d_cnt[NB];                     // self-restoring: scatter returns it to 0
static __device__ int d_offs[NB + 1];
static __device__ unsigned long long d_look[NBLK];
static __device__ int2 d_bpair[MAXN];                // (key, original idx) in bucket order
static __device__ int d_gidx[MAXN];
static __device__ int d_mi[MAXM];                    // output row r
static __device__ int d_mj[MAXM];
static __device__ int d_mk[MAXM];
static __device__ int d_mcount;
static __device__ __align__(16) __half d_Wh[4096];   // W[13]^T as half: [co][ci]

// ---------------- fused init + keys + histogram ----------------

__global__ void k_keys_hist(const int* __restrict__ coords, const float* __restrict__ W, int n) {
    __shared__ int sc[768];
    int tid = threadIdx.x;
    int t = blockIdx.x * 256 + tid;

    if (t < NBLK) d_look[t] = 0ull;
    if (t == 0) d_mcount = 0;
    if (t < 4096) {
        int co = t >> 6, ci = t & 63;
        d_Wh[t] = __float2half(W[13 * 4096 + ci * 64 + co]);
    }

    int base = blockIdx.x * 768;
#pragma unroll
    for (int x = tid; x < 768; x += 256) {
        int g = base + x;
        if (g < n * 3) sc[x] = coords[g];
    }
    __syncthreads();
    if (t >= n) return;
    int key = (sc[tid * 3] * SGRID + sc[tid * 3 + 1]) * SGRID + sc[tid * 3 + 2];
    d_keys[t] = key;
    atomicAdd(&d_cnt[key >> BSHIFT], 1);
}

// single-pass decoupled-lookback scan: 256 blocks x 1024 threads, co-resident
__global__ void __launch_bounds__(1024) k_scan() {
    __shared__ int sh[1024];
    __shared__ int sh_excl;
    int b = blockIdx.x, tid = threadIdx.x;
    int gid = b * 1024 + tid;
    int v = d_cnt[gid];
    sh[tid] = v;
#pragma unroll
    for (int off = 1; off < 1024; off <<= 1) {
        __syncthreads();
        int t = (tid >= off) ? sh[tid - off] : 0;
        __syncthreads();
        sh[tid] += t;
    }
    __syncthreads();
    if (tid == 0) {
        int agg = sh[1023];
        volatile unsigned long long* look = (volatile unsigned long long*)d_look;
        int excl = 0;
        if (b == 0) {
            look[0] = (2ull << 62) | (unsigned)agg;
        } else {
            look[b] = (1ull << 62) | (unsigned)agg;
            int j = b - 1;
            for (;;) {
                unsigned long long w = look[j];
                unsigned long long f = w >> 62;
                if (f == 0) continue;
                excl += (int)(w & 0x3FFFFFFFFFFFFFFFull);
                if (f == 2) break;
                j--;
            }
            look[b] = (2ull << 62) | (unsigned)(excl + agg);
        }
        sh_excl = excl;
    }
    __syncthreads();
    int base = sh_excl;
    d_offs[gid] = base + sh[tid] - v;
    if (gid == NB - 1) d_offs[NB] = base + sh[1023];
}

__global__ void k_scatter(int n) {
    int i = blockIdx.x * blockDim.x + threadIdx.x;
    if (i >= n) return;
    int key = d_keys[i];
    int b = key >> BSHIFT;
    int p = d_offs[b] + atomicSub(&d_cnt[b], 1) - 1;   // restores d_cnt[b] -> 0
    d_bpair[p] = make_int2(key, i);
}

// ---------------- fused rank + probe, iterated in SORTED POSITION order ----------------
// Warp-coherent: threads in a bucket share neighbor segments -> L1-hit dominated.

__global__ void __launch_bounds__(256) k_proberank(int n) {
    int p = blockIdx.x * blockDim.x + threadIdx.x;
    if (p >= n) return;
    int2 self = d_bpair[p];          // coalesced
    int key = self.x;
    int b = key >> BSHIFT;

    // rank within own bucket (entries adjacent to own load -> L1)
    int s0 = d_offs[b], e0 = d_offs[b + 1];
    int cnt = 0;
    for (int u = s0; u < e0; u++) cnt += (d_bpair[u].x < key);
    int r = s0 + cnt;
    d_gidx[r] = self.y;

    // batch all 9 (dx,dy) group bounds (broadcast-heavy within warp)
    int q[9], s[9], e[9];
#pragma unroll
    for (int g = 0; g < 9; g++) {
        int dq = (g / 3 - 1) * (SGRID * SGRID) + (g % 3 - 1) * SGRID;
        q[g] = key + dq;
        s[g] = d_offs[(q[g] - 1) >> BSHIFT];
        e[g] = d_offs[((q[g] + 1) >> BSHIFT) + 1];
    }

#pragma unroll
    for (int g = 0; g < 9; g++) {
        for (int u = s[g]; u < e[g]; u++) {
            int2 kv = d_bpair[u];
            int d = kv.x - q[g];
            if (d < -1 || d > 1) continue;
            if (d == 0 && g == 4) continue;   // self
            int pos = atomicAdd(&d_mcount, 1);
            if (pos < MAXM) {
                d_mi[pos] = r;
                d_mj[pos] = kv.y;
                d_mk[pos] = g * 3 + d + 1;
            }
        }
    }
}

// ---------------- dense gathered GEMM: fp16 mma.m16n8k16, M=128 x N=64, K=64 ----------------

#define FHP 72
#define WHP 72

__global__ void __launch_bounds__(128, 5) k_gemm_tc(const float* __restrict__ F,
                                                    float* __restrict__ out, int n) {
    __shared__ __align__(16) __half Ws[64 * WHP];
    __shared__ __align__(16) __half Fs[128 * FHP];
    int tid = threadIdx.x, lane = tid & 31, warp = tid >> 5;

#pragma unroll
    for (int k = 0; k < 8; k++) {
        int x = tid + 128 * k;
        int r = x >> 4, c = x & 15;
        uint2 v = ((const uint2*)d_Wh)[x];
        *(uint2*)&Ws[r * WHP + c * 4] = v;
    }

    int row0 = blockIdx.x * 128;
    {
        int gr = row0 + tid;
        int gi = d_gidx[(gr < n) ? gr : 0];
        const float4* src = (const float4*)(F + (size_t)gi * 64);
#pragma unroll
        for (int c = 0; c < 16; c++) {
            float4 v = src[c];
            *(__half2*)&Fs[tid * FHP + c * 4] = __floats2half2_rn(v.x, v.y);
            *(__half2*)&Fs[tid * FHP + c * 4 + 2] = __floats2half2_rn(v.z, v.w);
        }
    }
    __syncthreads();

    int g = lane >> 2, t = lane & 3;
    int mBase = warp * 32;
    float acc[2][8][4];
#pragma unroll
    for (int mt = 0; mt < 2; mt++)
#pragma unroll
        for (int nt = 0; nt < 8; nt++)
#pragma unroll
            for (int u = 0; u < 4; u++) acc[mt][nt][u] = 0.f;

#pragma unroll
    for (int k0 = 0; k0 < 64; k0 += 16) {
        unsigned a[2][4];
#pragma unroll
        for (int mt = 0; mt < 2; mt++) {
            int r = mBase + mt * 16;
            a[mt][0] = *(const unsigned*)&Fs[(r + g) * FHP + k0 + 2 * t];
            a[mt][1] = *(const unsigned*)&Fs[(r + g + 8) * FHP + k0 + 2 * t];
            a[mt][2] = *(const unsigned*)&Fs[(r + g) * FHP + k0 + 2 * t + 8];
            a[mt][3] = *(const unsigned*)&Fs[(r + g + 8) * FHP + k0 + 2 * t + 8];
        }
#pragma unroll
        for (int nt = 0; nt < 8; nt++) {
            unsigned b0 = *(const unsigned*)&Ws[(nt * 8 + g) * WHP + k0 + 2 * t];
            unsigned b1 = *(const unsigned*)&Ws[(nt * 8 + g) * WHP + k0 + 2 * t + 8];
#pragma unroll
            for (int mt = 0; mt < 2; mt++) {
                asm volatile(
                    "mma.sync.aligned.m16n8k16.row.col.f32.f16.f16.f32 "
                    "{%0,%1,%2,%3},{%4,%5,%6,%7},{%8,%9},{%0,%1,%2,%3};"
                    : "+f"(acc[mt][nt][0]), "+f"(acc[mt][nt][1]),
                      "+f"(acc[mt][nt][2]), "+f"(acc[mt][nt][3])
                    : "r"(a[mt][0]), "r"(a[mt][1]), "r"(a[mt][2]), "r"(a[mt][3]),
                      "r"(b0), "r"(b1));
            }
        }
    }

#pragma unroll
    for (int mt = 0; mt < 2; mt++) {
        int rA = row0 + mBase + mt * 16 + g;
        int rB = rA + 8;
#pragma unroll
        for (int nt = 0; nt < 8; nt++) {
            int c = nt * 8 + 2 * t;
            if (rA < n) *(float2*)&out[(size_t)rA * 64 + c] =
                make_float2(acc[mt][nt][0], acc[mt][nt][1]);
            if (rB < n) *(float2*)&out[(size_t)rB * 64 + c] =
                make_float2(acc[mt][nt][2], acc[mt][nt][3]);
        }
    }
}

// ---------------- apply corrections ----------------

__global__ void k_apply(const float* __restrict__ F, const float* __restrict__ W,
                        float* __restrict__ out) {
    int warp = (blockIdx.x * blockDim.x + threadIdx.x) >> 5;
    int lane = threadIdx.x & 31;
    int nwarps = (gridDim.x * blockDim.x) >> 5;
    int total = d_mcount;
    if (total > MAXM) total = MAXM;
    for (int m = warp; m < total; m += nwarps) {
        int r = d_mi[m], j = d_mj[m], k = d_mk[m];
        float fv0 = F[j * 64 + lane];
        float fv1 = F[j * 64 + 32 + lane];
        const float* Wk = W + k * 64 * 64;
        float a0 = 0.f, a1 = 0.f;
#pragma unroll
        for (int ci = 0; ci < 32; ci++) {
            float f = __shfl_sync(0xffffffffu, fv0, ci);
            a0 += f * Wk[ci * 64 + lane];
            a1 += f * Wk[ci * 64 + 32 + lane];
        }
#pragma unroll
        for (int ci = 0; ci < 32; ci++) {
            float f = __shfl_sync(0xffffffffu, fv1, ci);
            a0 += f * Wk[(ci + 32) * 64 + lane];
            a1 += f * Wk[(ci + 32) * 64 + 32 + lane];
        }
        atomicAdd(&out[r * 64 + lane], a0);
        atomicAdd(&out[r * 64 + 32 + lane], a1);
    }
}

// ---------------- launch ----------------

extern "C" void kernel_launch(void* const* d_in, const int* in_sizes, int n_in,
                              void* d_out, int out_size) {
    const float* F = (const float*)d_in[0];
    const float* W = (const float*)d_in[1];
    const int* coords = (const int*)d_in[2];
    int n = in_sizes[2] / 3;
    if (n > MAXN) n = MAXN;
    float* out = (float*)d_out;

    k_keys_hist<<<(n + 255) / 256, 256>>>(coords, W, n);
    k_scan<<<NBLK, 1024>>>();
    k_scatter<<<(n + 255) / 256, 256>>>(n);
    k_proberank<<<(n + 255) / 256, 256>>>(n);
    k_gemm_tc<<<(n + 127) / 128, 128>>>(F, out, n);
    k_apply<<<256, 256>>>(F, W, out);
}